// round 8
// baseline (speedup 1.0000x reference)
#include <cuda_runtime.h>
#include <cuda_bf16.h>
#include <cstdint>

// LGMLoss on GB300 — Round 8: single fused kernel, 128 CTAs x 512 threads.
// N-split (BM=32, BN=128) + depth-4 bulk-copy pipeline + rotated chunk order.
// Cross-CTA row reduction via global partials + monotonic ticket counters.

#define B_BATCH 2048
#define C_CLS   256
#define F_DIM   256
#define ALPHA_F 0.1f
#define EPS_F   1e-8f

#define BM      32
#define BN      128
#define NCHUNK  4              // K split: 4 chunks of 128 bf16 (64 features)
#define STR     272            // A smem row stride (256B + 16 pad)
#define B_CHUNK_BYTES 32768    // 128 rows x 256B

// ---------------- device scratch ----------------
// B' pre-swizzled, chunk-major: [4][256 rows][64 words]; word = bf16x2 (iv, -2m*iv)
__device__ uint32_t g_Bchunks[NCHUNK * C_CLS * 64];
__device__ float g_K[C_CLS];
__device__ float g_invden[C_CLS];
__device__ float g_ps[B_BATCH * 2];     // per-row partial sum   [row][half]
__device__ float g_pp[B_BATCH * 2];     // per-row partial p_lbl [row][half]
__device__ unsigned int g_done[B_BATCH / BM];   // per-row-group tickets (monotonic)
__device__ unsigned int g_bar;                  // epoch barrier (monotonic)

// ---------------- helpers ----------------
__device__ __forceinline__ uint32_t smem_u32(const void* p) {
    uint32_t a;
    asm("{ .reg .u64 t; cvta.to.shared.u64 t, %1; cvt.u32.u64 %0, t; }"
        : "=r"(a) : "l"(p));
    return a;
}
__device__ __forceinline__ void ldmatrix_x4(uint32_t* r, uint32_t addr) {
    asm volatile("ldmatrix.sync.aligned.m8n8.x4.shared.b16 {%0,%1,%2,%3}, [%4];"
                 : "=r"(r[0]), "=r"(r[1]), "=r"(r[2]), "=r"(r[3]) : "r"(addr));
}
__device__ __forceinline__ void mma16816(float* d, const uint32_t* a,
                                         uint32_t b0, uint32_t b1) {
    asm volatile(
        "mma.sync.aligned.m16n8k16.row.col.f32.bf16.bf16.f32 "
        "{%0,%1,%2,%3}, {%4,%5,%6,%7}, {%8,%9}, {%0,%1,%2,%3};"
        : "+f"(d[0]), "+f"(d[1]), "+f"(d[2]), "+f"(d[3])
        : "r"(a[0]), "r"(a[1]), "r"(a[2]), "r"(a[3]), "r"(b0), "r"(b1));
}
__device__ __forceinline__ uint32_t pack_pair(float x) {
    __nv_bfloat162 p = __floats2bfloat162_rn(x * x, x);   // (x^2, x)
    return *(uint32_t*)&p;
}
#define MBAR_INIT(a, n) \
    asm volatile("mbarrier.init.shared.b64 [%0], %1;" :: "r"(a), "r"(n) : "memory")
#define MBAR_EXPECT_TX(a, tx) \
    asm volatile("mbarrier.arrive.expect_tx.shared.b64 _, [%0], %1;" \
                 :: "r"(a), "r"(tx) : "memory")
#define MBAR_WAIT(a, ph) do { \
    asm volatile("{ .reg .pred P; WL%=: mbarrier.try_wait.parity.acquire.cta.shared::cta.b64 P, [%0], %1, 0x989680;" \
                 " @P bra WD%=; bra WL%=; WD%=: }" :: "r"(a), "r"(ph) : "memory"); \
} while (0)
__device__ __forceinline__ void bulk_copy(uint32_t dst, const void* src,
                                          uint32_t bytes, uint32_t mbar) {
    asm volatile(
        "cp.async.bulk.shared::cluster.global.mbarrier::complete_tx::bytes "
        "[%0], [%1], %2, [%3];"
        :: "r"(dst), "l"(src), "r"(bytes), "r"(mbar) : "memory");
}

// ---------------------------------------------------------------------------
// Smem layout (bytes):
//   0: sK(1K) | 1024: sInv(1K) | 2048: sPS(1K)+sPP(1K) | 4096: mbar[4]
//   4160: flag | 4352: A bufs 4 x 8704 | 39168: B bufs 4 x 32768
// total 170240 (>114K -> 1 CTA/SM, grid 128 co-resident)
// ---------------------------------------------------------------------------
#define SM_KOFF 0
#define SM_IOFF 1024
#define SM_RED  2048
#define SM_MBAR 4096
#define SM_FLAG 4160
#define SM_A    4352
#define A_BUFSZ 8704
#define SM_B    39168
#define SMEM_TOTAL 170240

__global__ __launch_bounds__(512, 1) void lgm_fused_kernel(
    const float* __restrict__ feat,
    const int* __restrict__ labels,
    const float* __restrict__ means,
    const float* __restrict__ vars_,
    float* __restrict__ out) {
    extern __shared__ char smem[];
    const int tid  = threadIdx.x;
    const int wid  = tid >> 5;
    const int lane = tid & 31;
    const int bid  = blockIdx.x;
    const int grp  = bid >> 1;           // row group (32 rows)
    const int hh   = bid & 1;            // col half: [hh*128, hh*128+128)
    const int bRow0 = grp * BM;
    const uint32_t sbase = smem_u32(smem);

    float* sK   = (float*)(smem + SM_KOFF);
    float* sInv = (float*)(smem + SM_IOFF);
    float* sPS  = (float*)(smem + SM_RED);          // [32 rows][8 warps]
    float* sPP  = sPS + 256;
    int*   sFlag = (int*)(smem + SM_FLAG);

    if (tid == 0) {
        #pragma unroll
        for (int i = 0; i < NCHUNK; i++) MBAR_INIT(sbase + SM_MBAR + i * 8, 1);
    }

    // ---- A prefetch (all 4 chunks) ----
    const float4* featv = (const float4*)feat;      // 64 float4 per row
    const int ar = tid >> 4, as = tid & 15;         // 32 rows x 16 segs
    float4 aReg[4];
    #pragma unroll
    for (int ci = 0; ci < NCHUNK; ci++)
        aReg[ci] = featv[(size_t)(bRow0 + ar) * 64 + ci * 16 + as];

    // ---------------- phase 1: per-class precompute (2 classes/CTA) --------
    {
        const int half = tid >> 8;            // 0/1 -> class
        const int tf   = tid & 255;           // feature
        const int c    = 2 * bid + half;
        float m = means[c * F_DIM + tf];
        float v = vars_[c * F_DIM + tf];
        float iv = 1.0f / (v + EPS_F);
        __nv_bfloat162 pp = __floats2bfloat162_rn(iv, -2.0f * m * iv);
        {   // swizzled chunk-major store
            int ci = tf >> 6, p = tf & 63;
            int idx = ci * (C_CLS * 64) + c * 64
                    + ((((p >> 2) ^ (c & 7)) << 2) | (p & 3));
            g_Bchunks[idx] = *(uint32_t*)&pp;
        }
        out[B_BATCH + c * F_DIM + tf] = m;                       // passthrough
        out[B_BATCH + C_CLS * F_DIM + c * F_DIM + tf] = v;

        float ks = m * m * iv;
        float pr = v;
        #pragma unroll
        for (int o = 16; o > 0; o >>= 1) {
            ks += __shfl_xor_sync(0xffffffffu, ks, o);
            pr *= __shfl_xor_sync(0xffffffffu, pr, o);
        }
        if (lane == 0) { sPS[wid] = ks; sPS[16 + wid] = pr; }    // reuse sPS
        __syncthreads();
        if (tf == 0) {
            float K = 0.0f, det = 1.0f;
            #pragma unroll
            for (int i = 0; i < 8; i++) {
                K += sPS[half * 8 + i];
                det *= sPS[16 + half * 8 + i];
            }
            g_K[c] = K;
            g_invden[c] = 1.0f / (det * det + EPS_F);
        }
    }
    // stage all A chunks (independent of B')
    #pragma unroll
    for (int ci = 0; ci < NCHUNK; ci++) {
        float4 v = aReg[ci];
        uint4 w;
        w.x = pack_pair(v.x); w.y = pack_pair(v.y);
        w.z = pack_pair(v.z); w.w = pack_pair(v.w);
        *(uint4*)(smem + SM_A + ci * A_BUFSZ + ar * STR + as * 16) = w;
    }

    // ---------------- device-wide epoch barrier ----------------
    const int start = bid & 3;            // rotated chunk order
    __syncthreads();
    if (tid == 0) {
        __threadfence();
        unsigned tk = atomicAdd(&g_bar, 1u);
        unsigned target = (tk & ~127u) + 128u;
        unsigned cur;
        do {
            asm volatile("ld.acquire.gpu.global.b32 %0, [%1];"
                         : "=r"(cur) : "l"(&g_bar));
        } while (cur < target);
        asm volatile("fence.proxy.async;" ::: "memory");
        #pragma unroll
        for (int i = 0; i < NCHUNK; i++) {
            int ci = (start + i) & 3;
            uint32_t mb = sbase + SM_MBAR + ci * 8;
            MBAR_EXPECT_TX(mb, B_CHUNK_BYTES);
            bulk_copy(sbase + SM_B + ci * B_CHUNK_BYTES,
                      g_Bchunks + ci * (C_CLS * 64) + hh * (BN * 64),
                      B_CHUNK_BYTES, mb);
        }
    }
    __syncthreads();
    if (tid < C_CLS) {                    // valid after barrier
        sK[tid]   = g_K[tid];
        sInv[tid] = g_invden[tid];
    }

    // ---------------- phase 2: GEMM mainloop ----------------
    const int mg = wid >> 3;              // m-group: rows mg*16..+15
    const int wn = wid & 7;               // n-group: cols wn*16..+15 (local)
    float acc[2][4] = {};
    #pragma unroll
    for (int i = 0; i < NCHUNK; i++) {
        const int ci = (start + i) & 3;
        MBAR_WAIT(sbase + SM_MBAR + ci * 8, 0);
        const uint32_t sAu = sbase + SM_A + ci * A_BUFSZ;
        const uint32_t sBu = sbase + SM_B + ci * B_CHUNK_BYTES;
        #pragma unroll
        for (int ks = 0; ks < 8; ks++) {
            uint32_t a[4], b[4];
            ldmatrix_x4(a, sAu + (uint32_t)(mg * 16 + (lane & 15)) * STR
                           + (uint32_t)(ks * 32 + ((lane >> 4) & 1) * 16));
            {
                int brow = wn * 16 + (lane & 7) + ((lane >> 4) & 1) * 8;
                int bseg = ks * 2 + ((lane >> 3) & 1);
                ldmatrix_x4(b, sBu + (uint32_t)(brow * 256
                                  + ((bseg ^ (brow & 7)) << 4)));
            }
            mma16816(acc[0], a, b[0], b[1]);
            mma16816(acc[1], a, b[2], b[3]);
        }
    }

    // ---------------- epilogue: prob + partial row sums ----------------
    const int r0 = lane >> 2;
    const int lbl0 = labels[bRow0 + mg * 16 + r0];
    const int lbl1 = labels[bRow0 + mg * 16 + r0 + 8];
    const int colBase = hh * BN + wn * 16;
    float s0 = 0.f, s1 = 0.f, pl0 = 0.f, pl1 = 0.f;
    #pragma unroll
    for (int nt = 0; nt < 2; nt++) {
        int c0 = colBase + nt * 8 + (lane & 3) * 2;
        int c1 = c0 + 1;
        float k0 = sK[c0], k1 = sK[c1];
        float i0 = sInv[c0], i1 = sInv[c1];
        {
            float d0 = 0.5f * (acc[nt][0] + k0);
            float d1 = 0.5f * (acc[nt][1] + k1);
            if (c0 == lbl0) d0 *= (1.0f + ALPHA_F);
            if (c1 == lbl0) d1 *= (1.0f + ALPHA_F);
            float p0 = __expf(-d0) * i0;
            float p1 = __expf(-d1) * i1;
            s0 += p0 + p1;
            if (c0 == lbl0) pl0 += p0;
            if (c1 == lbl0) pl0 += p1;
        }
        {
            float d0 = 0.5f * (acc[nt][2] + k0);
            float d1 = 0.5f * (acc[nt][3] + k1);
            if (c0 == lbl1) d0 *= (1.0f + ALPHA_F);
            if (c1 == lbl1) d1 *= (1.0f + ALPHA_F);
            float p0 = __expf(-d0) * i0;
            float p1 = __expf(-d1) * i1;
            s1 += p0 + p1;
            if (c0 == lbl1) pl1 += p0;
            if (c1 == lbl1) pl1 += p1;
        }
    }
    #pragma unroll
    for (int o = 1; o < 4; o <<= 1) {
        s0  += __shfl_xor_sync(0xffffffffu, s0, o);
        s1  += __shfl_xor_sync(0xffffffffu, s1, o);
        pl0 += __shfl_xor_sync(0xffffffffu, pl0, o);
        pl1 += __shfl_xor_sync(0xffffffffu, pl1, o);
    }
    __syncthreads();                      // sPS free (phase-1 reuse done)
    if ((lane & 3) == 0) {
        int rA = mg * 16 + r0;
        sPS[rA * 8 + wn]       = s0;
        sPS[(rA + 8) * 8 + wn] = s1;
        sPP[rA * 8 + wn]       = pl0;
        sPP[(rA + 8) * 8 + wn] = pl1;
    }
    __syncthreads();

    // ---------------- cross-CTA combine (monotonic ticket) ----------------
    if (tid < BM) {
        float s = 0.f, pl = 0.f;
        #pragma unroll
        for (int w = 0; w < 8; w++) {
            s  += sPS[tid * 8 + w];
            pl += sPP[tid * 8 + w];
        }
        g_ps[(bRow0 + tid) * 2 + hh] = s;
        g_pp[(bRow0 + tid) * 2 + hh] = pl;
        __threadfence();
    }
    __syncthreads();
    if (tid == 0) {
        unsigned tk = atomicAdd(&g_done[grp], 1u);
        *sFlag = (int)(tk & 1u);          // odd ticket = second arriver
    }
    __syncthreads();
    if (*sFlag && tid < BM) {
        __threadfence();
        int b = bRow0 + tid;
        float s  = g_ps[b * 2] + g_ps[b * 2 + 1];
        float pl = g_pp[b * 2] + g_pp[b * 2 + 1];
        out[b] = -logf(pl / (s + EPS_F) + EPS_F);
    }
}

// ---------------------------------------------------------------------------
extern "C" void kernel_launch(void* const* d_in, const int* in_sizes, int n_in,
                              void* d_out, int out_size) {
    const float* feat   = (const float*)d_in[0];
    const int*   labels = (const int*)d_in[1];
    const float* means  = (const float*)d_in[2];
    const float* vars_  = (const float*)d_in[3];
    float* out = (float*)d_out;

    cudaFuncSetAttribute(lgm_fused_kernel,
                         cudaFuncAttributeMaxDynamicSharedMemorySize, SMEM_TOTAL);

    lgm_fused_kernel<<<128, 512, SMEM_TOTAL>>>(feat, labels, means, vars_, out);
}